// round 15
// baseline (speedup 1.0000x reference)
#include <cuda_runtime.h>
#include <cuda_fp16.h>
#include <cstdint>
#include <cstddef>

#define T_TOK 8192
#define HDIM  4096
#define NEXP  8
#define BM 128
#define BN 128
#define BK 64
#define KT (HDIM / BK)                       // 64
#define CAP_ROWS (2 * T_TOK + NEXP * BM)     // 17408
#define MAX_TILES (CAP_ROWS / BM)            // 136
#define NCOL (HDIM / BN)                     // 32
#define SAS 72                               // smem row stride in halves
#define A_STG (BM * SAS)                     // 9216 halves
#define B_STG (BN * SAS)                     // 9216 halves
#define NSTAGE 3
#define SMEM_DYN (NSTAGE * (A_STG + B_STG) * 2)   // 110592 B (x2 CTAs = 221184)
#define NTHR 256
#define NPERS 296                            // persistent CTAs: 2 per SM x 148

#define W_N8 ((size_t)NEXP * HDIM * HDIM / 8)     // 16777216
#define X_N8 ((size_t)T_TOK * HDIM / 8)           // 4194304
#define GATE_BLOCKS (T_TOK / 8)                   // 1024

// -------- device scratch (static; no runtime allocation) --------
__device__ __half g_w[(size_t)NEXP * HDIM * HDIM];   // fp16-rounded weights
__device__ __half g_xh[(size_t)T_TOK * HDIM];        // fp16 x (contiguous, per token)
__device__ int g_cnt[NEXP], g_fill[NEXP], g_base[NEXP];
__device__ int g_exp0[T_TOK], g_exp1[T_TOK];
__device__ int g_rowtok[CAP_ROWS];                   // grouped row -> token (-1 = pad)
__device__ int g_tile_e[MAX_TILES], g_tile_r[MAX_TILES];
__device__ int g_ntiles;

// -------- helpers --------
__device__ __forceinline__ uint32_t smem_u32(const void* p) {
    uint32_t a;
    asm("{ .reg .u64 t; cvta.to.shared.u64 t, %1; cvt.u32.u64 %0, t; }"
        : "=r"(a) : "l"(p));
    return a;
}

__device__ __forceinline__ void cp16(uint32_t d, const void* s) {
    asm volatile("cp.async.cg.shared.global [%0], [%1], 16;" :: "r"(d), "l"(s));
}

__device__ __forceinline__ void mma16(float* c, const uint32_t* a, const uint32_t* b) {
    asm volatile(
        "mma.sync.aligned.m16n8k16.row.col.f32.f16.f16.f32 "
        "{%0,%1,%2,%3}, {%4,%5,%6,%7}, {%8,%9}, {%0,%1,%2,%3};"
        : "+f"(c[0]), "+f"(c[1]), "+f"(c[2]), "+f"(c[3])
        : "r"(a[0]), "r"(a[1]), "r"(a[2]), "r"(a[3]), "r"(b[0]), "r"(b[1]));
}

__device__ __forceinline__ void ldm4(uint32_t* r, uint32_t addr) {
    asm volatile("ldmatrix.sync.aligned.m8n8.x4.shared.b16 {%0,%1,%2,%3}, [%4];"
                 : "=r"(r[0]), "=r"(r[1]), "=r"(r[2]), "=r"(r[3]) : "r"(addr));
}

__device__ __forceinline__ void red2(float* p, float a, float b) {
    asm volatile("red.global.add.f32 [%0], %1;" :: "l"(p), "f"(a) : "memory");
    asm volatile("red.global.add.f32 [%0], %1;" :: "l"(p + 1), "f"(b) : "memory");
}

__device__ __forceinline__ uint2 cvt4(float4 v) {
    __half2 h0 = __floats2half2_rn(v.x, v.y);
    __half2 h1 = __floats2half2_rn(v.z, v.w);
    uint2 o;
    o.x = *(uint32_t*)&h0;
    o.y = *(uint32_t*)&h1;
    return o;
}

// -------- kernel 1: fused pre-pass --------
__global__ void k_pre(const float* __restrict__ x, const float* __restrict__ gw,
                      const float* __restrict__ ew) {
    if (blockIdx.x < GATE_BLOCKS) {
        int t = blockIdx.x * 8 + (threadIdx.x >> 5);
        int lane = threadIdx.x & 31;
        const float4* xr = (const float4*)(x + (size_t)t * HDIM);
        const float4* gr = (const float4*)gw;
        float acc[NEXP];
#pragma unroll
        for (int e = 0; e < NEXP; e++) acc[e] = 0.f;
        for (int i = lane; i < HDIM / 4; i += 32) {
            float4 xv = xr[i];
#pragma unroll
            for (int e = 0; e < NEXP; e++) {
                float4 wv = gr[e * (HDIM / 4) + i];
                acc[e] += xv.x * wv.x + xv.y * wv.y + xv.z * wv.z + xv.w * wv.w;
            }
        }
#pragma unroll
        for (int o = 16; o > 0; o >>= 1)
#pragma unroll
            for (int e = 0; e < NEXP; e++)
                acc[e] += __shfl_xor_sync(0xFFFFFFFFu, acc[e], o);
        if (lane == 0) {
            float v0 = -1e30f, v1 = -1e30f; int i0 = 0, i1 = 1;
#pragma unroll
            for (int e = 0; e < NEXP; e++) {
                float v = acc[e];
                if (v > v0) { v1 = v0; i1 = i0; v0 = v; i0 = e; }
                else if (v > v1) { v1 = v; i1 = e; }
            }
            g_exp0[t] = i0; g_exp1[t] = i1;
            atomicAdd(&g_cnt[i0], 1);
            atomicAdd(&g_cnt[i1], 1);
        }
        return;
    }
    size_t nconv = W_N8 + X_N8;
    size_t nthr = (size_t)(gridDim.x - GATE_BLOCKS) * blockDim.x;
    size_t start = (size_t)(blockIdx.x - GATE_BLOCKS) * blockDim.x + threadIdx.x;
    const float4* wsrc = (const float4*)ew;
    const float4* xsrc = (const float4*)x;
    uint4* wdst = (uint4*)g_w;
    uint4* xdst = (uint4*)g_xh;
    for (size_t i = start; i < nconv; i += nthr) {
        if (i < W_N8) {
            uint2 a = cvt4(wsrc[2 * i]), b = cvt4(wsrc[2 * i + 1]);
            wdst[i] = make_uint4(a.x, a.y, b.x, b.y);
        } else {
            size_t j = i - W_N8;
            uint2 a = cvt4(xsrc[2 * j]), b = cvt4(xsrc[2 * j + 1]);
            xdst[j] = make_uint4(a.x, a.y, b.x, b.y);
        }
    }
}

// -------- kernel 2: prefix sum + tile map (1 thread) --------
__global__ void k_scan() {
    if (threadIdx.x != 0 || blockIdx.x != 0) return;
    int total = 0, nt = 0;
    for (int e = 0; e < NEXP; e++) {
        g_base[e] = total;
        int tl = (g_cnt[e] + BM - 1) / BM;
        for (int i = 0; i < tl; i++) { g_tile_e[nt] = e; g_tile_r[nt] = total + i * BM; nt++; }
        total += tl * BM;
    }
    g_ntiles = nt;
}

// -------- kernel 3: assign grouped positions --------
__global__ void k_assign() {
    int t = blockIdx.x * blockDim.x + threadIdx.x;
    if (t >= T_TOK) return;
    int e0 = g_exp0[t], e1 = g_exp1[t];
    int p0 = g_base[e0] + atomicAdd(&g_fill[e0], 1);
    int p1 = g_base[e1] + atomicAdd(&g_fill[e1], 1);
    g_rowtok[p0] = t;
    g_rowtok[p1] = t;
}

// -------- kernel 4: persistent grouped GEMM, fp16 m16n8k16 + ldmatrix --------
// 296 persistent CTAs (2/SM), each loops over jobs = (tile, ncol).
// Per job: 128x128x64 tile, 3-stage cp.async, 8 warps 2(M)x4(N), 64x32/warp.
__global__ void __launch_bounds__(NTHR, 2) k_gemm(float* __restrict__ out) {
    extern __shared__ __half sm[];
    __half* sAb = sm;                       // 3 stages of A
    __half* sBb = sm + NSTAGE * A_STG;      // 3 stages of B

    int tid = threadIdx.x, lane = tid & 31, warp = tid >> 5;
    int wm = warp >> 2, wn = warp & 3;      // 2(M) x 4(N)

    // per-lane ldmatrix offsets (in halves)
    int aLdm = (wm * 64 + (lane & 15)) * SAS + (lane >> 4) * 8;
    int bLdm = (wn * 32 + (lane & 7) + ((lane >> 4) << 3)) * SAS + (((lane >> 3) & 1) << 3);

    int njobs = g_ntiles * NCOL;

    for (int job = blockIdx.x; job < njobs; job += NPERS) {
        int ty = job >> 5;            // tile index (y)
        int n0 = (job & 31) * BN;     // n column block
        int e = g_tile_e[ty];
        int row0 = g_tile_r[ty];
        const __half* gB = g_w + (size_t)e * HDIM * HDIM + (size_t)n0 * HDIM;

        // A producer: per-thread indirect row pointers (constant across kt)
        const __half* aSrc[4];
        int aOff[4];
#pragma unroll
        for (int i = 0; i < 4; i++) {
            int ch = tid + i * NTHR;
            int r = ch >> 3, c = ch & 7;
            int tok = g_rowtok[row0 + r];
            if (tok < 0) tok = 0;
            aSrc[i] = g_xh + (size_t)tok * HDIM + c * 8;
            aOff[i] = r * SAS + c * 8;
        }

        float acc[4][4][4];
#pragma unroll
        for (int i = 0; i < 4; i++)
#pragma unroll
            for (int j = 0; j < 4; j++)
#pragma unroll
                for (int k = 0; k < 4; k++) acc[i][j][k] = 0.f;

#define LOAD_STAGE(S, K0) do {                                               \
    __half* _sa = sAb + (S) * A_STG;                                         \
    __half* _sb = sBb + (S) * B_STG;                                         \
    const __half* _gb = gB + (K0);                                           \
    _Pragma("unroll")                                                        \
    for (int _i = 0; _i < 4; _i++)                                           \
        cp16(smem_u32(_sa + aOff[_i]), aSrc[_i] + (K0));                     \
    _Pragma("unroll")                                                        \
    for (int _i = 0; _i < 4; _i++) {                                         \
        int _ch = tid + _i * NTHR; int _r = _ch >> 3, _c = _ch & 7;          \
        cp16(smem_u32(_sb + _r * SAS + _c * 8), _gb + (size_t)_r * HDIM + _c * 8); \
    }                                                                        \
    asm volatile("cp.async.commit_group;" ::: "memory");                     \
} while (0)

        LOAD_STAGE(0, 0);
        LOAD_STAGE(1, BK);

        for (int kt = 0; kt < KT; kt++) {
            if (kt + 1 == KT) asm volatile("cp.async.wait_group 0;" ::: "memory");
            else              asm volatile("cp.async.wait_group 1;" ::: "memory");
            __syncthreads();

            int cur = kt % NSTAGE;
            uint32_t aBase = smem_u32(sAb + cur * A_STG + aLdm);
            uint32_t bBase = smem_u32(sBb + cur * B_STG + bLdm);
#pragma unroll
            for (int ks = 0; ks < 4; ks++) {
                uint32_t af[4][4], bf[4][2];
#pragma unroll
                for (int i = 0; i < 4; i++)
                    ldm4(af[i], aBase + (i * 16 * SAS + ks * 16) * 2);
#pragma unroll
                for (int jj = 0; jj < 2; jj++) {
                    uint32_t r[4];
                    ldm4(r, bBase + (jj * 16 * SAS + ks * 16) * 2);
                    bf[2 * jj][0] = r[0]; bf[2 * jj][1] = r[1];
                    bf[2 * jj + 1][0] = r[2]; bf[2 * jj + 1][1] = r[3];
                }
#pragma unroll
                for (int i = 0; i < 4; i++)
#pragma unroll
                    for (int j = 0; j < 4; j++)
                        mma16(acc[i][j], af[i], bf[j]);
            }

            if (kt + 2 < KT) LOAD_STAGE((kt + 2) % NSTAGE, (kt + 2) * BK);
        }
        // all warps done reading smem before next job overwrites stage 0
        __syncthreads();

        // epilogue: scatter-reduce rows into out by token (pad rows skipped)
#pragma unroll
        for (int i = 0; i < 4; i++) {
            int rl = wm * 64 + i * 16 + (lane >> 2);
            int tok0 = g_rowtok[row0 + rl];
            int tok1 = g_rowtok[row0 + rl + 8];
            float* o0 = out + (size_t)tok0 * HDIM;
            float* o1 = out + (size_t)tok1 * HDIM;
#pragma unroll
            for (int j = 0; j < 4; j++) {
                int c0 = n0 + wn * 32 + j * 8 + 2 * (lane & 3);
                if (tok0 >= 0) red2(o0 + c0, acc[i][j][0], acc[i][j][1]);
                if (tok1 >= 0) red2(o1 + c0, acc[i][j][2], acc[i][j][3]);
            }
        }
#undef LOAD_STAGE
    }
}

extern "C" void kernel_launch(void* const* d_in, const int* in_sizes, int n_in,
                              void* d_out, int out_size) {
    const float* x  = (const float*)d_in[0];   // [8192, 4096]
    const float* gw = (const float*)d_in[1];   // [8, 4096]
    const float* ew = (const float*)d_in[2];   // [8, 4096, 4096]
    float* out = (float*)d_out;                // [8192, 4096]
    (void)in_sizes; (void)n_in; (void)out_size;

    cudaFuncSetAttribute(k_gemm, cudaFuncAttributeMaxDynamicSharedMemorySize, SMEM_DYN);

    void *pcnt, *pfill, *prt;
    cudaGetSymbolAddress(&pcnt, g_cnt);
    cudaGetSymbolAddress(&pfill, g_fill);
    cudaGetSymbolAddress(&prt, g_rowtok);

    cudaMemsetAsync(pcnt, 0, NEXP * sizeof(int));
    cudaMemsetAsync(pfill, 0, NEXP * sizeof(int));
    cudaMemsetAsync(prt, 0xFF, CAP_ROWS * sizeof(int));        // -1
    cudaMemsetAsync(d_out, 0, (size_t)T_TOK * HDIM * sizeof(float));

    k_pre<<<GATE_BLOCKS + 65536, 256>>>(x, gw, ew);
    k_scan<<<1, 1>>>();
    k_assign<<<(T_TOK + 255) / 256, 256>>>();
    k_gemm<<<NPERS, NTHR, SMEM_DYN>>>(out);
}

// round 16
// speedup vs baseline: 1.0496x; 1.0496x over previous
#include <cuda_runtime.h>
#include <cuda_fp16.h>
#include <cstdint>
#include <cstddef>

#define T_TOK 8192
#define HDIM  4096
#define NEXP  8
#define BM 128
#define BN 128
#define BK 64
#define KSPLIT 2
#define KHALF (HDIM / KSPLIT)                // 2048
#define KT (KHALF / BK)                      // 32
#define CAP_ROWS (2 * T_TOK + NEXP * BM)     // 17408
#define MAX_TILES (CAP_ROWS / BM)            // 136
#define SAS 72                               // smem row stride in halves
#define A_STG (BM * SAS)                     // 9216 halves
#define B_STG (BN * SAS)                     // 9216 halves
#define NSTAGE 3
#define SMEM_DYN (NSTAGE * (A_STG + B_STG) * 2)   // 110592 B (x2 CTAs = 221184)
#define NTHR 256

#define W_N8 ((size_t)NEXP * HDIM * HDIM / 8)
#define X_N8 ((size_t)T_TOK * HDIM / 8)
#define GATE_BLOCKS (T_TOK / 8)              // 1024

// -------- device scratch (static; no runtime allocation) --------
__device__ __half g_w[(size_t)NEXP * HDIM * HDIM];   // fp16-rounded weights
__device__ __half g_xh[(size_t)T_TOK * HDIM];        // fp16 x (contiguous, per token)
__device__ int g_cnt[NEXP], g_fill[NEXP], g_base[NEXP];
__device__ int g_exp0[T_TOK], g_exp1[T_TOK];
__device__ int g_rowtok[CAP_ROWS];                   // grouped row -> token (-1 = pad)
__device__ int g_tile_e[MAX_TILES], g_tile_r[MAX_TILES];
__device__ int g_ntiles;

// -------- helpers --------
__device__ __forceinline__ uint32_t smem_u32(const void* p) {
    uint32_t a;
    asm("{ .reg .u64 t; cvta.to.shared.u64 t, %1; cvt.u32.u64 %0, t; }"
        : "=r"(a) : "l"(p));
    return a;
}

__device__ __forceinline__ void cp16(uint32_t d, const void* s) {
    asm volatile("cp.async.cg.shared.global [%0], [%1], 16;" :: "r"(d), "l"(s));
}

__device__ __forceinline__ void mma16(float* c, const uint32_t* a, const uint32_t* b) {
    asm volatile(
        "mma.sync.aligned.m16n8k16.row.col.f32.f16.f16.f32 "
        "{%0,%1,%2,%3}, {%4,%5,%6,%7}, {%8,%9}, {%0,%1,%2,%3};"
        : "+f"(c[0]), "+f"(c[1]), "+f"(c[2]), "+f"(c[3])
        : "r"(a[0]), "r"(a[1]), "r"(a[2]), "r"(a[3]), "r"(b[0]), "r"(b[1]));
}

__device__ __forceinline__ void ldm4(uint32_t* r, uint32_t addr) {
    asm volatile("ldmatrix.sync.aligned.m8n8.x4.shared.b16 {%0,%1,%2,%3}, [%4];"
                 : "=r"(r[0]), "=r"(r[1]), "=r"(r[2]), "=r"(r[3]) : "r"(addr));
}

__device__ __forceinline__ void red2(float* p, float a, float b) {
    asm volatile("red.global.add.f32 [%0], %1;" :: "l"(p), "f"(a) : "memory");
    asm volatile("red.global.add.f32 [%0], %1;" :: "l"(p + 1), "f"(b) : "memory");
}

__device__ __forceinline__ uint2 cvt4(float4 v) {
    __half2 h0 = __floats2half2_rn(v.x, v.y);
    __half2 h1 = __floats2half2_rn(v.z, v.w);
    uint2 o;
    o.x = *(uint32_t*)&h0;
    o.y = *(uint32_t*)&h1;
    return o;
}

// -------- kernel 1: fused pre-pass --------
__global__ void k_pre(const float* __restrict__ x, const float* __restrict__ gw,
                      const float* __restrict__ ew) {
    if (blockIdx.x < GATE_BLOCKS) {
        int t = blockIdx.x * 8 + (threadIdx.x >> 5);
        int lane = threadIdx.x & 31;
        const float4* xr = (const float4*)(x + (size_t)t * HDIM);
        const float4* gr = (const float4*)gw;
        float acc[NEXP];
#pragma unroll
        for (int e = 0; e < NEXP; e++) acc[e] = 0.f;
        for (int i = lane; i < HDIM / 4; i += 32) {
            float4 xv = xr[i];
#pragma unroll
            for (int e = 0; e < NEXP; e++) {
                float4 wv = gr[e * (HDIM / 4) + i];
                acc[e] += xv.x * wv.x + xv.y * wv.y + xv.z * wv.z + xv.w * wv.w;
            }
        }
#pragma unroll
        for (int o = 16; o > 0; o >>= 1)
#pragma unroll
            for (int e = 0; e < NEXP; e++)
                acc[e] += __shfl_xor_sync(0xFFFFFFFFu, acc[e], o);
        if (lane == 0) {
            float v0 = -1e30f, v1 = -1e30f; int i0 = 0, i1 = 1;
#pragma unroll
            for (int e = 0; e < NEXP; e++) {
                float v = acc[e];
                if (v > v0) { v1 = v0; i1 = i0; v0 = v; i0 = e; }
                else if (v > v1) { v1 = v; i1 = e; }
            }
            g_exp0[t] = i0; g_exp1[t] = i1;
            atomicAdd(&g_cnt[i0], 1);
            atomicAdd(&g_cnt[i1], 1);
        }
        return;
    }
    size_t nconv = W_N8 + X_N8;
    size_t nthr = (size_t)(gridDim.x - GATE_BLOCKS) * blockDim.x;
    size_t start = (size_t)(blockIdx.x - GATE_BLOCKS) * blockDim.x + threadIdx.x;
    const float4* wsrc = (const float4*)ew;
    const float4* xsrc = (const float4*)x;
    uint4* wdst = (uint4*)g_w;
    uint4* xdst = (uint4*)g_xh;
    for (size_t i = start; i < nconv; i += nthr) {
        if (i < W_N8) {
            uint2 a = cvt4(wsrc[2 * i]), b = cvt4(wsrc[2 * i + 1]);
            wdst[i] = make_uint4(a.x, a.y, b.x, b.y);
        } else {
            size_t j = i - W_N8;
            uint2 a = cvt4(xsrc[2 * j]), b = cvt4(xsrc[2 * j + 1]);
            xdst[j] = make_uint4(a.x, a.y, b.x, b.y);
        }
    }
}

// -------- kernel 2: prefix sum + tile map (1 thread) --------
__global__ void k_scan() {
    if (threadIdx.x != 0 || blockIdx.x != 0) return;
    int total = 0, nt = 0;
    for (int e = 0; e < NEXP; e++) {
        g_base[e] = total;
        int tl = (g_cnt[e] + BM - 1) / BM;
        for (int i = 0; i < tl; i++) { g_tile_e[nt] = e; g_tile_r[nt] = total + i * BM; nt++; }
        total += tl * BM;
    }
    g_ntiles = nt;
}

// -------- kernel 3: assign grouped positions --------
__global__ void k_assign() {
    int t = blockIdx.x * blockDim.x + threadIdx.x;
    if (t >= T_TOK) return;
    int e0 = g_exp0[t], e1 = g_exp1[t];
    int p0 = g_base[e0] + atomicAdd(&g_fill[e0], 1);
    int p1 = g_base[e1] + atomicAdd(&g_fill[e1], 1);
    g_rowtok[p0] = t;
    g_rowtok[p1] = t;
}

// -------- kernel 4: grouped GEMM, fp16 m16n8k16 + ldmatrix, 128x128 tile --------
// Split-K=2: blockIdx.z selects K half (2048). 256 threads = 8 warps, 2(M)x4(N),
// 64x32 per warp; 2 CTAs per SM; 3-stage cp.async pipeline.
// Epilogue scatter-reduces into out (red.global.add, 4 adds/element total).
__global__ void __launch_bounds__(NTHR, 2) k_gemm(float* __restrict__ out) {
    if ((int)blockIdx.y >= g_ntiles) return;
    extern __shared__ __half sm[];
    __half* sAb = sm;                       // 3 stages of A
    __half* sBb = sm + NSTAGE * A_STG;      // 3 stages of B

    int tid = threadIdx.x, lane = tid & 31, warp = tid >> 5;
    int wm = warp >> 2, wn = warp & 3;      // 2(M) x 4(N)

    int e = g_tile_e[blockIdx.y];
    int row0 = g_tile_r[blockIdx.y];
    int n0 = blockIdx.x * BN;
    int k0base = blockIdx.z * KHALF;
    const __half* gB = g_w + (size_t)e * HDIM * HDIM + (size_t)n0 * HDIM + k0base;

    // A producer: per-thread indirect row pointers (constant across kt)
    const __half* aSrc[4];
    int aOff[4];
#pragma unroll
    for (int i = 0; i < 4; i++) {
        int ch = tid + i * NTHR;
        int r = ch >> 3, c = ch & 7;
        int tok = g_rowtok[row0 + r];
        if (tok < 0) tok = 0;
        aSrc[i] = g_xh + (size_t)tok * HDIM + k0base + c * 8;
        aOff[i] = r * SAS + c * 8;
    }

    // per-lane ldmatrix offsets (in halves)
    int aLdm = (wm * 64 + (lane & 15)) * SAS + (lane >> 4) * 8;
    int bLdm = (wn * 32 + (lane & 7) + ((lane >> 4) << 3)) * SAS + (((lane >> 3) & 1) << 3);

    float acc[4][4][4];
#pragma unroll
    for (int i = 0; i < 4; i++)
#pragma unroll
        for (int j = 0; j < 4; j++)
#pragma unroll
            for (int k = 0; k < 4; k++) acc[i][j][k] = 0.f;

#define LOAD_STAGE(S, K0) do {                                               \
    __half* _sa = sAb + (S) * A_STG;                                         \
    __half* _sb = sBb + (S) * B_STG;                                         \
    const __half* _gb = gB + (K0);                                           \
    _Pragma("unroll")                                                        \
    for (int _i = 0; _i < 4; _i++)                                           \
        cp16(smem_u32(_sa + aOff[_i]), aSrc[_i] + (K0));                     \
    _Pragma("unroll")                                                        \
    for (int _i = 0; _i < 4; _i++) {                                         \
        int _ch = tid + _i * NTHR; int _r = _ch >> 3, _c = _ch & 7;          \
        cp16(smem_u32(_sb + _r * SAS + _c * 8), _gb + (size_t)_r * HDIM + _c * 8); \
    }                                                                        \
    asm volatile("cp.async.commit_group;" ::: "memory");                     \
} while (0)

    LOAD_STAGE(0, 0);
    LOAD_STAGE(1, BK);

    for (int kt = 0; kt < KT; kt++) {
        if (kt + 1 == KT) asm volatile("cp.async.wait_group 0;" ::: "memory");
        else              asm volatile("cp.async.wait_group 1;" ::: "memory");
        __syncthreads();

        int cur = kt % NSTAGE;
        uint32_t aBase = smem_u32(sAb + cur * A_STG + aLdm);
        uint32_t bBase = smem_u32(sBb + cur * B_STG + bLdm);
#pragma unroll
        for (int ks = 0; ks < 4; ks++) {
            uint32_t af[4][4], bf[4][2];
#pragma unroll
            for (int i = 0; i < 4; i++)
                ldm4(af[i], aBase + (i * 16 * SAS + ks * 16) * 2);
#pragma unroll
            for (int jj = 0; jj < 2; jj++) {
                uint32_t r[4];
                ldm4(r, bBase + (jj * 16 * SAS + ks * 16) * 2);
                bf[2 * jj][0] = r[0]; bf[2 * jj][1] = r[1];
                bf[2 * jj + 1][0] = r[2]; bf[2 * jj + 1][1] = r[3];
            }
#pragma unroll
            for (int i = 0; i < 4; i++)
#pragma unroll
                for (int j = 0; j < 4; j++)
                    mma16(acc[i][j], af[i], bf[j]);
        }

        if (kt + 2 < KT) LOAD_STAGE((kt + 2) % NSTAGE, (kt + 2) * BK);
    }

    // epilogue: scatter-reduce rows into out by token (pad rows skipped)
#pragma unroll
    for (int i = 0; i < 4; i++) {
        int rl = wm * 64 + i * 16 + (lane >> 2);
        int tok0 = g_rowtok[row0 + rl];
        int tok1 = g_rowtok[row0 + rl + 8];
        float* o0 = out + (size_t)tok0 * HDIM;
        float* o1 = out + (size_t)tok1 * HDIM;
#pragma unroll
        for (int j = 0; j < 4; j++) {
            int c0 = n0 + wn * 32 + j * 8 + 2 * (lane & 3);
            if (tok0 >= 0) red2(o0 + c0, acc[i][j][0], acc[i][j][1]);
            if (tok1 >= 0) red2(o1 + c0, acc[i][j][2], acc[i][j][3]);
        }
    }
#undef LOAD_STAGE
}

extern "C" void kernel_launch(void* const* d_in, const int* in_sizes, int n_in,
                              void* d_out, int out_size) {
    const float* x  = (const float*)d_in[0];   // [8192, 4096]
    const float* gw = (const float*)d_in[1];   // [8, 4096]
    const float* ew = (const float*)d_in[2];   // [8, 4096, 4096]
    float* out = (float*)d_out;                // [8192, 4096]
    (void)in_sizes; (void)n_in; (void)out_size;

    cudaFuncSetAttribute(k_gemm, cudaFuncAttributeMaxDynamicSharedMemorySize, SMEM_DYN);

    void *pcnt, *pfill, *prt;
    cudaGetSymbolAddress(&pcnt, g_cnt);
    cudaGetSymbolAddress(&pfill, g_fill);
    cudaGetSymbolAddress(&prt, g_rowtok);

    cudaMemsetAsync(pcnt, 0, NEXP * sizeof(int));
    cudaMemsetAsync(pfill, 0, NEXP * sizeof(int));
    cudaMemsetAsync(prt, 0xFF, CAP_ROWS * sizeof(int));        // -1
    cudaMemsetAsync(d_out, 0, (size_t)T_TOK * HDIM * sizeof(float));

    k_pre<<<GATE_BLOCKS + 65536, 256>>>(x, gw, ew);
    k_scan<<<1, 1>>>();
    k_assign<<<(T_TOK + 255) / 256, 256>>>();
    k_gemm<<<dim3(HDIM / BN, MAX_TILES, KSPLIT), NTHR, SMEM_DYN>>>(out);
}

// round 17
// speedup vs baseline: 1.1005x; 1.0486x over previous
#include <cuda_runtime.h>
#include <cuda_fp16.h>
#include <cstdint>
#include <cstddef>

#define T_TOK 8192
#define HDIM  4096
#define NEXP  8
#define BM 128
#define BN 128
#define BK 64
#define KT (HDIM / BK)                       // 64
#define CAP_ROWS (2 * T_TOK + NEXP * BM)     // 17408
#define MAX_TILES (CAP_ROWS / BM)            // 136
#define SAS 72                               // smem row stride in halves
#define A_STG (BM * SAS)                     // 9216 halves
#define B_STG (BN * SAS)                     // 9216 halves
#define NSTAGE 3
#define SMEM_DYN (NSTAGE * (A_STG + B_STG) * 2)   // 110592 B (x2 CTAs = 221184)
#define NTHR 256

#define W_N8 ((size_t)NEXP * HDIM * HDIM / 8)
#define X_N8 ((size_t)T_TOK * HDIM / 8)
#define GATE_BLOCKS (T_TOK / 8)              // 1024

// -------- device scratch (static; no runtime allocation) --------
__device__ __half g_w[(size_t)NEXP * HDIM * HDIM];   // fp16-rounded weights
__device__ __half g_xh[(size_t)T_TOK * HDIM];        // fp16 x (contiguous, per token)
__device__ int g_cnt[NEXP], g_fill[NEXP], g_base[NEXP];
__device__ int g_exp0[T_TOK], g_exp1[T_TOK];
__device__ int g_rowtok[CAP_ROWS];                   // grouped row -> token (-1 = pad)
__device__ int g_tile_e[MAX_TILES], g_tile_r[MAX_TILES];
__device__ int g_ntiles;

// -------- helpers --------
__device__ __forceinline__ uint32_t smem_u32(const void* p) {
    uint32_t a;
    asm("{ .reg .u64 t; cvta.to.shared.u64 t, %1; cvt.u32.u64 %0, t; }"
        : "=r"(a) : "l"(p));
    return a;
}

__device__ __forceinline__ void cp16(uint32_t d, const void* s) {
    asm volatile("cp.async.cg.shared.global [%0], [%1], 16;" :: "r"(d), "l"(s));
}

__device__ __forceinline__ void mma16(float* c, const uint32_t* a, const uint32_t* b) {
    asm volatile(
        "mma.sync.aligned.m16n8k16.row.col.f32.f16.f16.f32 "
        "{%0,%1,%2,%3}, {%4,%5,%6,%7}, {%8,%9}, {%0,%1,%2,%3};"
        : "+f"(c[0]), "+f"(c[1]), "+f"(c[2]), "+f"(c[3])
        : "r"(a[0]), "r"(a[1]), "r"(a[2]), "r"(a[3]), "r"(b[0]), "r"(b[1]));
}

__device__ __forceinline__ void ldm4(uint32_t* r, uint32_t addr) {
    asm volatile("ldmatrix.sync.aligned.m8n8.x4.shared.b16 {%0,%1,%2,%3}, [%4];"
                 : "=r"(r[0]), "=r"(r[1]), "=r"(r[2]), "=r"(r[3]) : "r"(addr));
}

__device__ __forceinline__ void red2(float* p, float a, float b) {
    asm volatile("red.global.add.f32 [%0], %1;" :: "l"(p), "f"(a) : "memory");
    asm volatile("red.global.add.f32 [%0], %1;" :: "l"(p + 1), "f"(b) : "memory");
}

__device__ __forceinline__ uint2 cvt4(float4 v) {
    __half2 h0 = __floats2half2_rn(v.x, v.y);
    __half2 h1 = __floats2half2_rn(v.z, v.w);
    uint2 o;
    o.x = *(uint32_t*)&h0;
    o.y = *(uint32_t*)&h1;
    return o;
}

// -------- kernel 1: fused pre-pass --------
__global__ void k_pre(const float* __restrict__ x, const float* __restrict__ gw,
                      const float* __restrict__ ew) {
    if (blockIdx.x < GATE_BLOCKS) {
        int t = blockIdx.x * 8 + (threadIdx.x >> 5);
        int lane = threadIdx.x & 31;
        const float4* xr = (const float4*)(x + (size_t)t * HDIM);
        const float4* gr = (const float4*)gw;
        float acc[NEXP];
#pragma unroll
        for (int e = 0; e < NEXP; e++) acc[e] = 0.f;
        for (int i = lane; i < HDIM / 4; i += 32) {
            float4 xv = xr[i];
#pragma unroll
            for (int e = 0; e < NEXP; e++) {
                float4 wv = gr[e * (HDIM / 4) + i];
                acc[e] += xv.x * wv.x + xv.y * wv.y + xv.z * wv.z + xv.w * wv.w;
            }
        }
#pragma unroll
        for (int o = 16; o > 0; o >>= 1)
#pragma unroll
            for (int e = 0; e < NEXP; e++)
                acc[e] += __shfl_xor_sync(0xFFFFFFFFu, acc[e], o);
        if (lane == 0) {
            float v0 = -1e30f, v1 = -1e30f; int i0 = 0, i1 = 1;
#pragma unroll
            for (int e = 0; e < NEXP; e++) {
                float v = acc[e];
                if (v > v0) { v1 = v0; i1 = i0; v0 = v; i0 = e; }
                else if (v > v1) { v1 = v; i1 = e; }
            }
            g_exp0[t] = i0; g_exp1[t] = i1;
            atomicAdd(&g_cnt[i0], 1);
            atomicAdd(&g_cnt[i1], 1);
        }
        return;
    }
    size_t nconv = W_N8 + X_N8;
    size_t nthr = (size_t)(gridDim.x - GATE_BLOCKS) * blockDim.x;
    size_t start = (size_t)(blockIdx.x - GATE_BLOCKS) * blockDim.x + threadIdx.x;
    const float4* wsrc = (const float4*)ew;
    const float4* xsrc = (const float4*)x;
    uint4* wdst = (uint4*)g_w;
    uint4* xdst = (uint4*)g_xh;
    for (size_t i = start; i < nconv; i += nthr) {
        if (i < W_N8) {
            uint2 a = cvt4(wsrc[2 * i]), b = cvt4(wsrc[2 * i + 1]);
            wdst[i] = make_uint4(a.x, a.y, b.x, b.y);
        } else {
            size_t j = i - W_N8;
            uint2 a = cvt4(xsrc[2 * j]), b = cvt4(xsrc[2 * j + 1]);
            xdst[j] = make_uint4(a.x, a.y, b.x, b.y);
        }
    }
}

// -------- kernel 2: prefix sum + tile map (1 thread) --------
__global__ void k_scan() {
    if (threadIdx.x != 0 || blockIdx.x != 0) return;
    int total = 0, nt = 0;
    for (int e = 0; e < NEXP; e++) {
        g_base[e] = total;
        int tl = (g_cnt[e] + BM - 1) / BM;
        for (int i = 0; i < tl; i++) { g_tile_e[nt] = e; g_tile_r[nt] = total + i * BM; nt++; }
        total += tl * BM;
    }
    g_ntiles = nt;
}

// -------- kernel 3: assign grouped positions --------
__global__ void k_assign() {
    int t = blockIdx.x * blockDim.x + threadIdx.x;
    if (t >= T_TOK) return;
    int e0 = g_exp0[t], e1 = g_exp1[t];
    int p0 = g_base[e0] + atomicAdd(&g_fill[e0], 1);
    int p1 = g_base[e1] + atomicAdd(&g_fill[e1], 1);
    g_rowtok[p0] = t;
    g_rowtok[p1] = t;
}

// -------- kernel 4: grouped GEMM, fp16 m16n8k16 + ldmatrix, 128x128x64, 3-stage --------
// 256 threads = 8 warps in a 2(M) x 4(N) grid, 64x32 per warp; 2 CTAs per SM.
// Loop: wait_group -> __syncthreads -> consume(kt) with LOAD_STAGE(kt+2) issued
// mid-block (after ks=1) so the next stage's flight starts ~half a kt earlier
// without delaying the current stage's ldmatrix chain.
__global__ void __launch_bounds__(NTHR, 2) k_gemm(float* __restrict__ out) {
    if ((int)blockIdx.y >= g_ntiles) return;
    extern __shared__ __half sm[];
    __half* sAb = sm;                       // 3 stages of A
    __half* sBb = sm + NSTAGE * A_STG;      // 3 stages of B

    int tid = threadIdx.x, lane = tid & 31, warp = tid >> 5;
    int wm = warp >> 2, wn = warp & 3;      // 2(M) x 4(N)

    int e = g_tile_e[blockIdx.y];
    int row0 = g_tile_r[blockIdx.y];
    int n0 = blockIdx.x * BN;
    const __half* gB = g_w + (size_t)e * HDIM * HDIM + (size_t)n0 * HDIM;

    // A producer: per-thread indirect row pointers (constant across kt)
    const __half* aSrc[4];
    int aOff[4];
#pragma unroll
    for (int i = 0; i < 4; i++) {
        int ch = tid + i * NTHR;
        int r = ch >> 3, c = ch & 7;
        int tok = g_rowtok[row0 + r];
        if (tok < 0) tok = 0;
        aSrc[i] = g_xh + (size_t)tok * HDIM + c * 8;
        aOff[i] = r * SAS + c * 8;
    }

    // per-lane ldmatrix offsets (in halves)
    int aLdm = (wm * 64 + (lane & 15)) * SAS + (lane >> 4) * 8;
    int bLdm = (wn * 32 + (lane & 7) + ((lane >> 4) << 3)) * SAS + (((lane >> 3) & 1) << 3);

    float acc[4][4][4];
#pragma unroll
    for (int i = 0; i < 4; i++)
#pragma unroll
        for (int j = 0; j < 4; j++)
#pragma unroll
            for (int k = 0; k < 4; k++) acc[i][j][k] = 0.f;

#define LOAD_STAGE(S, K0) do {                                               \
    __half* _sa = sAb + (S) * A_STG;                                         \
    __half* _sb = sBb + (S) * B_STG;                                         \
    const __half* _gb = gB + (K0);                                           \
    _Pragma("unroll")                                                        \
    for (int _i = 0; _i < 4; _i++)                                           \
        cp16(smem_u32(_sa + aOff[_i]), aSrc[_i] + (K0));                     \
    _Pragma("unroll")                                                        \
    for (int _i = 0; _i < 4; _i++) {                                         \
        int _ch = tid + _i * NTHR; int _r = _ch >> 3, _c = _ch & 7;          \
        cp16(smem_u32(_sb + _r * SAS + _c * 8), _gb + (size_t)_r * HDIM + _c * 8); \
    }                                                                        \
    asm volatile("cp.async.commit_group;" ::: "memory");                     \
} while (0)

    LOAD_STAGE(0, 0);
    LOAD_STAGE(1, BK);

    for (int kt = 0; kt < KT; kt++) {
        if (kt + 1 == KT) asm volatile("cp.async.wait_group 0;" ::: "memory");
        else              asm volatile("cp.async.wait_group 1;" ::: "memory");
        __syncthreads();

        int cur = kt % NSTAGE;
        uint32_t aBase = smem_u32(sAb + cur * A_STG + aLdm);
        uint32_t bBase = smem_u32(sBb + cur * B_STG + bLdm);
#pragma unroll
        for (int ks = 0; ks < 4; ks++) {
            uint32_t af[4][4], bf[4][2];
#pragma unroll
            for (int i = 0; i < 4; i++)
                ldm4(af[i], aBase + (i * 16 * SAS + ks * 16) * 2);
#pragma unroll
            for (int jj = 0; jj < 2; jj++) {
                uint32_t r[4];
                ldm4(r, bBase + (jj * 16 * SAS + ks * 16) * 2);
                bf[2 * jj][0] = r[0]; bf[2 * jj][1] = r[1];
                bf[2 * jj + 1][0] = r[2]; bf[2 * jj + 1][1] = r[3];
            }
#pragma unroll
            for (int i = 0; i < 4; i++)
#pragma unroll
                for (int j = 0; j < 4; j++)
                    mma16(acc[i][j], af[i], bf[j]);

            // mid-block producer: start next stage's flight after half the
            // mma work, behind this stage's ldmatrix chain
            if (ks == 1 && kt + 2 < KT)
                LOAD_STAGE((kt + 2) % NSTAGE, (kt + 2) * BK);
        }
    }

    // epilogue: scatter-reduce rows into out by token (pad rows skipped)
#pragma unroll
    for (int i = 0; i < 4; i++) {
        int rl = wm * 64 + i * 16 + (lane >> 2);
        int tok0 = g_rowtok[row0 + rl];
        int tok1 = g_rowtok[row0 + rl + 8];
        float* o0 = out + (size_t)tok0 * HDIM;
        float* o1 = out + (size_t)tok1 * HDIM;
#pragma unroll
        for (int j = 0; j < 4; j++) {
            int c0 = n0 + wn * 32 + j * 8 + 2 * (lane & 3);
            if (tok0 >= 0) red2(o0 + c0, acc[i][j][0], acc[i][j][1]);
            if (tok1 >= 0) red2(o1 + c0, acc[i][j][2], acc[i][j][3]);
        }
    }
#undef LOAD_STAGE
}

extern "C" void kernel_launch(void* const* d_in, const int* in_sizes, int n_in,
                              void* d_out, int out_size) {
    const float* x  = (const float*)d_in[0];   // [8192, 4096]
    const float* gw = (const float*)d_in[1];   // [8, 4096]
    const float* ew = (const float*)d_in[2];   // [8, 4096, 4096]
    float* out = (float*)d_out;                // [8192, 4096]
    (void)in_sizes; (void)n_in; (void)out_size;

    cudaFuncSetAttribute(k_gemm, cudaFuncAttributeMaxDynamicSharedMemorySize, SMEM_DYN);

    void *pcnt, *pfill, *prt;
    cudaGetSymbolAddress(&pcnt, g_cnt);
    cudaGetSymbolAddress(&pfill, g_fill);
    cudaGetSymbolAddress(&prt, g_rowtok);

    cudaMemsetAsync(pcnt, 0, NEXP * sizeof(int));
    cudaMemsetAsync(pfill, 0, NEXP * sizeof(int));
    cudaMemsetAsync(prt, 0xFF, CAP_ROWS * sizeof(int));        // -1
    cudaMemsetAsync(d_out, 0, (size_t)T_TOK * HDIM * sizeof(float));

    k_pre<<<GATE_BLOCKS + 65536, 256>>>(x, gw, ew);
    k_scan<<<1, 1>>>();
    k_assign<<<(T_TOK + 255) / 256, 256>>>();
    k_gemm<<<dim3(HDIM / BN, MAX_TILES), NTHR, SMEM_DYN>>>(out);
}